// round 1
// baseline (speedup 1.0000x reference)
#include <cuda_runtime.h>
#include <math.h>

#define Nn   4
#define CIN  1024
#define CB   256
#define Hh   56
#define Ww   56
#define HW   3136
#define KT   9

// Scratch (device globals: allocation-free rule)
__device__ float g_r  [Nn * CB * HW];     // conv1 output (relu)
__device__ float g_off[Nn * 2 * KT * HW]; // offset conv output
__device__ float g_r2 [Nn * CB * HW];     // deform conv output (relu)
__device__ float g_w2t[CB * KT * CB];     // w2 transposed to [c*9+tap][o]

// ---------------------------------------------------------------------------
// w2 (o,c,kh,kw) -> g_w2t[(c*9+tap)*256 + o]
// ---------------------------------------------------------------------------
__global__ void transpose_w2_kernel(const float* __restrict__ w2) {
    int i = blockIdx.x * 256 + threadIdx.x;
    if (i < CB * KT * CB) {
        int k = i / CB;        // c*9+tap
        int o = i % CB;
        int c = k / KT;
        int t = k % KT;
        g_w2t[i] = w2[(o * CB + c) * KT + t];
    }
}

// ---------------------------------------------------------------------------
// 1x1 conv as GEMM: C[n][m][p] = relu(bias[m] + resid? + sum_k A[m][k]*B[n][k][p])
// 64x64 tile, BK=16, 4x4 microtile, 256 threads
// ---------------------------------------------------------------------------
#define BM 64
#define BN 64
#define BKk 16

__global__ void conv1x1_kernel(const float* __restrict__ A,      // [M][Kd]
                               const float* __restrict__ Bx,     // [Nn][Kd][HW]
                               const float* __restrict__ bias,   // [M]
                               const float* __restrict__ resid,  // [Nn][M][HW] or null
                               float* __restrict__ C,            // [Nn][M][HW]
                               int M, int Kd) {
    __shared__ float As[BKk][BM];
    __shared__ float Bs[BKk][BN];

    const int n  = blockIdx.z;
    const int m0 = blockIdx.y * BM;
    const int p0 = blockIdx.x * BN;
    const int tid = threadIdx.x;
    const float* Bn = Bx + (size_t)n * Kd * HW;

    float acc[4][4] = {};
    const int tm = tid >> 4;           // 0..15
    const int tn = tid & 15;           // 0..15

    const int arow = tid >> 2;         // 0..63
    const int acol = (tid & 3) << 2;   // 0,4,8,12
    const int brow = tid >> 4;         // 0..15
    const int bcol = (tid & 15) << 2;  // 0..60

    for (int k0 = 0; k0 < Kd; k0 += BKk) {
        float4 av = *(const float4*)(A + (size_t)(m0 + arow) * Kd + k0 + acol);
        As[acol + 0][arow] = av.x;
        As[acol + 1][arow] = av.y;
        As[acol + 2][arow] = av.z;
        As[acol + 3][arow] = av.w;
        float4 bv = *(const float4*)(Bn + (size_t)(k0 + brow) * HW + p0 + bcol);
        *(float4*)&Bs[brow][bcol] = bv;
        __syncthreads();
#pragma unroll
        for (int kk = 0; kk < BKk; ++kk) {
            float4 a = *(const float4*)&As[kk][tm << 2];
            float4 b = *(const float4*)&Bs[kk][tn << 2];
            float ar[4] = {a.x, a.y, a.z, a.w};
            float br[4] = {b.x, b.y, b.z, b.w};
#pragma unroll
            for (int i = 0; i < 4; ++i)
#pragma unroll
                for (int j = 0; j < 4; ++j)
                    acc[i][j] += ar[i] * br[j];
        }
        __syncthreads();
    }

#pragma unroll
    for (int i = 0; i < 4; ++i) {
        int m = m0 + (tm << 2) + i;
        float bb = bias[m];
        size_t base = ((size_t)n * M + m) * HW + p0 + (tn << 2);
        float rx = 0.f, ry = 0.f, rz = 0.f, rw = 0.f;
        if (resid) {
            float4 rv = *(const float4*)(resid + base);
            rx = rv.x; ry = rv.y; rz = rv.z; rw = rv.w;
        }
        float4 o;
        o.x = fmaxf(acc[i][0] + bb + rx, 0.f);
        o.y = fmaxf(acc[i][1] + bb + ry, 0.f);
        o.z = fmaxf(acc[i][2] + bb + rz, 0.f);
        o.w = fmaxf(acc[i][3] + bb + rw, 0.f);
        *(float4*)(C + base) = o;
    }
}

// ---------------------------------------------------------------------------
// Offset conv: 3x3 SAME, CB=256 -> 18 channels, input g_r, output g_off.
// Block: 256 threads = 8 ci-groups x 32 pixel lanes; 64 pixels per block
// (each thread handles 2 pixels, all 18 oc). Reduce over groups in smem.
// ---------------------------------------------------------------------------
__global__ void offset_conv_kernel(const float* __restrict__ w_off,
                                   const float* __restrict__ b_off) {
    __shared__ float red[8][64][18];
    const int n  = blockIdx.y;
    const int p0 = blockIdx.x * 64;
    const int tid = threadIdx.x;
    const int g  = tid >> 5;   // 0..7
    const int lx = tid & 31;   // 0..31

    float acc[2][18];
#pragma unroll
    for (int q = 0; q < 2; ++q)
#pragma unroll
        for (int oc = 0; oc < 18; ++oc) acc[q][oc] = 0.f;

    for (int ci = g; ci < CB; ci += 8) {
        const float* rb = g_r + ((size_t)n * CB + ci) * HW;
        float v[2][9];
#pragma unroll
        for (int q = 0; q < 2; ++q) {
            int p = p0 + lx + q * 32;
            int h = p / Ww, w = p % Ww;
#pragma unroll
            for (int t = 0; t < 9; ++t) {
                int y = h + t / 3 - 1;
                int x = w + t % 3 - 1;
                v[q][t] = (y >= 0 && y < Hh && x >= 0 && x < Ww) ? rb[y * Ww + x] : 0.f;
            }
        }
        const float* wb = w_off + ci * 9;
#pragma unroll
        for (int oc = 0; oc < 18; ++oc) {
#pragma unroll
            for (int t = 0; t < 9; ++t) {
                float wv = wb[oc * (CB * 9) + t];  // broadcast within warp
                acc[0][oc] += wv * v[0][t];
                acc[1][oc] += wv * v[1][t];
            }
        }
    }

#pragma unroll
    for (int q = 0; q < 2; ++q)
#pragma unroll
        for (int oc = 0; oc < 18; ++oc)
            red[g][lx + q * 32][oc] = acc[q][oc];
    __syncthreads();

    for (int i = tid; i < 64 * 18; i += 256) {
        int ps = i / 18, oc = i % 18;
        float s = b_off[oc];
#pragma unroll
        for (int g2 = 0; g2 < 8; ++g2) s += red[g2][ps][oc];
        g_off[((size_t)n * 18 + oc) * HW + p0 + ps] = s;
    }
}

// ---------------------------------------------------------------------------
// Deformable 3x3 conv: implicit GEMM M=256(o), K=2304(c*9), 32 pixels/block.
// Phase A: precompute 4 corner indices + weights per (tap,px).
// Main loop over c in steps of 4: gather s[cc][tap][px] to smem, then
// each thread (oq,pg) accumulates 4 o x 8 px.
// ---------------------------------------------------------------------------
#define DP  32
#define CST 4

__global__ void deform_kernel(const float* __restrict__ b2) {
    __shared__ int   s_idx[4][9][DP];
    __shared__ float s_wt [4][9][DP];
    __shared__ float s_val[CST][9][DP];

    const int blk = blockIdx.x;
    const int n  = blk / (HW / DP);
    const int pb = (blk % (HW / DP)) * DP;
    const int tid = threadIdx.x;

    for (int i = tid; i < 9 * DP; i += 256) {
        int tap = i / DP, px = i % DP;
        int p = pb + px;
        int h = p / Ww, w = p % Ww;
        const float* offb = g_off + (size_t)n * 18 * HW + p;
        float dy = offb[(size_t)(tap * 2 + 0) * HW];
        float dx = offb[(size_t)(tap * 2 + 1) * HW];
        float ys = (float)(h + tap / 3 - 1) + dy;
        float xs = (float)(w + tap % 3 - 1) + dx;
        float y0f = floorf(ys), x0f = floorf(xs);
        float wy1 = ys - y0f, wy0 = 1.f - wy1;
        float wx1 = xs - x0f, wx0 = 1.f - wx1;
        int y0 = (int)y0f, x0 = (int)x0f;
#pragma unroll
        for (int c = 0; c < 4; ++c) {
            int yi = y0 + (c >> 1);
            int xi = x0 + (c & 1);
            bool ok = (yi >= 0) && (yi < Hh) && (xi >= 0) && (xi < Ww);
            int yc = min(max(yi, 0), Hh - 1);
            int xc = min(max(xi, 0), Ww - 1);
            s_idx[c][tap][px] = yc * Ww + xc;
            float wgt = ((c >> 1) ? wy1 : wy0) * ((c & 1) ? wx1 : wx0);
            s_wt[c][tap][px] = ok ? wgt : 0.f;
        }
    }
    __syncthreads();

    float acc[4][8] = {};
    const int oq  = tid >> 2;      // 0..63 -> o quad
    const int pg  = tid & 3;       // 0..3  -> pixel group
    const int px0 = pg << 3;

    for (int cb = 0; cb < CB; cb += CST) {
        for (int i = tid; i < CST * 9 * DP; i += 256) {
            int cc  = i / (9 * DP);
            int rem = i % (9 * DP);
            int tap = rem / DP, px = rem % DP;
            const float* fb = g_r + ((size_t)n * CB + cb + cc) * HW;
            float vsum = s_wt[0][tap][px] * fb[s_idx[0][tap][px]];
            vsum      += s_wt[1][tap][px] * fb[s_idx[1][tap][px]];
            vsum      += s_wt[2][tap][px] * fb[s_idx[2][tap][px]];
            vsum      += s_wt[3][tap][px] * fb[s_idx[3][tap][px]];
            s_val[cc][tap][px] = vsum;
        }
        __syncthreads();
#pragma unroll
        for (int cc = 0; cc < CST; ++cc) {
            const float4* wrow = (const float4*)(g_w2t + (size_t)(cb + cc) * (9 * CB));
#pragma unroll
            for (int tap = 0; tap < 9; ++tap) {
                float4 wv = wrow[tap * 64 + oq];
                float4 sa = *(const float4*)&s_val[cc][tap][px0];
                float4 sb = *(const float4*)&s_val[cc][tap][px0 + 4];
                float sv[8] = {sa.x, sa.y, sa.z, sa.w, sb.x, sb.y, sb.z, sb.w};
                float wr[4] = {wv.x, wv.y, wv.z, wv.w};
#pragma unroll
                for (int i = 0; i < 4; ++i)
#pragma unroll
                    for (int j = 0; j < 8; ++j)
                        acc[i][j] += wr[i] * sv[j];
            }
        }
        __syncthreads();
    }

#pragma unroll
    for (int i = 0; i < 4; ++i) {
        int o = (oq << 2) + i;
        float bb = b2[o];
        float* orow = g_r2 + ((size_t)n * CB + o) * HW + pb + px0;
        float4 o0, o1;
        o0.x = fmaxf(acc[i][0] + bb, 0.f);
        o0.y = fmaxf(acc[i][1] + bb, 0.f);
        o0.z = fmaxf(acc[i][2] + bb, 0.f);
        o0.w = fmaxf(acc[i][3] + bb, 0.f);
        o1.x = fmaxf(acc[i][4] + bb, 0.f);
        o1.y = fmaxf(acc[i][5] + bb, 0.f);
        o1.z = fmaxf(acc[i][6] + bb, 0.f);
        o1.w = fmaxf(acc[i][7] + bb, 0.f);
        *(float4*)orow       = o0;
        *(float4*)(orow + 4) = o1;
    }
}

// ---------------------------------------------------------------------------
extern "C" void kernel_launch(void* const* d_in, const int* in_sizes, int n_in,
                              void* d_out, int out_size) {
    const float* x     = (const float*)d_in[0];
    const float* w1    = (const float*)d_in[1];
    const float* b1    = (const float*)d_in[2];
    const float* w_off = (const float*)d_in[3];
    const float* b_off = (const float*)d_in[4];
    const float* w2    = (const float*)d_in[5];
    const float* b2    = (const float*)d_in[6];
    const float* w3    = (const float*)d_in[7];
    const float* b3    = (const float*)d_in[8];
    float* out = (float*)d_out;

    float *r_ptr, *r2_ptr;
    cudaGetSymbolAddress((void**)&r_ptr, g_r);
    cudaGetSymbolAddress((void**)&r2_ptr, g_r2);

    // w2 transpose (independent of data path; cheap)
    transpose_w2_kernel<<<(CB * KT * CB + 255) / 256, 256>>>(w2);

    // conv1: 1024 -> 256, relu
    conv1x1_kernel<<<dim3(HW / BN, CB / BM, Nn), 256>>>(w1, x, b1, nullptr, r_ptr,
                                                        CB, CIN);

    // offset conv 3x3: 256 -> 18
    offset_conv_kernel<<<dim3(HW / 64, Nn), 256>>>(w_off, b_off);

    // deformable conv 3x3: 256 -> 256, relu
    deform_kernel<<<Nn * (HW / DP), 256>>>(b2);

    // conv3: 256 -> 1024 + x residual, relu
    conv1x1_kernel<<<dim3(HW / BN, CIN / BM, Nn), 256>>>(w3, r2_ptr, b3, x, out,
                                                         CIN, CB);
}

// round 2
// speedup vs baseline: 1.0619x; 1.0619x over previous
#include <cuda_runtime.h>
#include <math.h>

#define Nn   4
#define CIN  1024
#define CB   256
#define Hh   56
#define Ww   56
#define HW   3136
#define KT   9

// Scratch (device globals: allocation-free rule)
__device__ float g_r  [Nn * CB * HW];     // conv1 output (relu)
__device__ float g_off[Nn * 2 * KT * HW]; // offset conv output
__device__ float g_r2 [Nn * CB * HW];     // deform conv output (relu)
__device__ float g_w2t[CB * KT * CB];     // w2 transposed to [c*9+tap][o]

// ---------------------------------------------------------------------------
// w2 (o,c,kh,kw) -> g_w2t[(c*9+tap)*256 + o]
// ---------------------------------------------------------------------------
__global__ void transpose_w2_kernel(const float* __restrict__ w2) {
    int i = blockIdx.x * 256 + threadIdx.x;
    if (i < CB * KT * CB) {
        int k = i / CB;        // c*9+tap
        int o = i % CB;
        int c = k / KT;
        int t = k % KT;
        g_w2t[i] = w2[(o * CB + c) * KT + t];
    }
}

// ---------------------------------------------------------------------------
// 1x1 conv as GEMM: C[n][m][p] = relu(bias[m] + resid? + sum_k A[m][k]*B[n][k][p])
// 128x64 tile, BK=16, 8x4 microtile, 256 threads
// ---------------------------------------------------------------------------
#define BM 128
#define BN 64
#define BKk 16

__global__ __launch_bounds__(256) void conv1x1_kernel(
        const float* __restrict__ A,      // [M][Kd]
        const float* __restrict__ Bx,     // [Nn][Kd][HW]
        const float* __restrict__ bias,   // [M]
        const float* __restrict__ resid,  // [Nn][M][HW] or null
        float* __restrict__ C,            // [Nn][M][HW]
        int M, int Kd) {
    __shared__ float As[BKk][BM];
    __shared__ float Bs[BKk][BN];

    const int n  = blockIdx.z;
    const int m0 = blockIdx.y * BM;
    const int p0 = blockIdx.x * BN;
    const int tid = threadIdx.x;
    const float* Bn = Bx + (size_t)n * Kd * HW;

    float acc[8][4] = {};
    const int tm = tid >> 4;           // 0..15 -> m oct
    const int tn = tid & 15;           // 0..15 -> px quad

    // A: 128 rows x 16 cols = 2048 floats; 8 per thread (two float4)
    const int arow = tid & 127;           // 0..127 (warp-contiguous rows)
    const int acol = (tid >> 7) << 3;     // 0 or 8
    // B: 16 rows x 64 cols = 1024 floats; 4 per thread (one float4)
    const int brow = tid >> 4;            // 0..15
    const int bcol = (tid & 15) << 2;     // 0..60

    for (int k0 = 0; k0 < Kd; k0 += BKk) {
        float4 av0 = *(const float4*)(A + (size_t)(m0 + arow) * Kd + k0 + acol);
        float4 av1 = *(const float4*)(A + (size_t)(m0 + arow) * Kd + k0 + acol + 4);
        As[acol + 0][arow] = av0.x;
        As[acol + 1][arow] = av0.y;
        As[acol + 2][arow] = av0.z;
        As[acol + 3][arow] = av0.w;
        As[acol + 4][arow] = av1.x;
        As[acol + 5][arow] = av1.y;
        As[acol + 6][arow] = av1.z;
        As[acol + 7][arow] = av1.w;
        float4 bv = *(const float4*)(Bn + (size_t)(k0 + brow) * HW + p0 + bcol);
        *(float4*)&Bs[brow][bcol] = bv;
        __syncthreads();
#pragma unroll
        for (int kk = 0; kk < BKk; ++kk) {
            float4 a0 = *(const float4*)&As[kk][tm << 3];
            float4 a1 = *(const float4*)&As[kk][(tm << 3) + 4];
            float4 b  = *(const float4*)&Bs[kk][tn << 2];
            float ar[8] = {a0.x, a0.y, a0.z, a0.w, a1.x, a1.y, a1.z, a1.w};
            float br[4] = {b.x, b.y, b.z, b.w};
#pragma unroll
            for (int i = 0; i < 8; ++i)
#pragma unroll
                for (int j = 0; j < 4; ++j)
                    acc[i][j] += ar[i] * br[j];
        }
        __syncthreads();
    }

#pragma unroll
    for (int i = 0; i < 8; ++i) {
        int m = m0 + (tm << 3) + i;
        float bb = bias[m];
        size_t base = ((size_t)n * M + m) * HW + p0 + (tn << 2);
        float rx = 0.f, ry = 0.f, rz = 0.f, rw = 0.f;
        if (resid) {
            float4 rv = *(const float4*)(resid + base);
            rx = rv.x; ry = rv.y; rz = rv.z; rw = rv.w;
        }
        float4 o;
        o.x = fmaxf(acc[i][0] + bb + rx, 0.f);
        o.y = fmaxf(acc[i][1] + bb + ry, 0.f);
        o.z = fmaxf(acc[i][2] + bb + rz, 0.f);
        o.w = fmaxf(acc[i][3] + bb + rw, 0.f);
        *(float4*)(C + base) = o;
    }
}

// ---------------------------------------------------------------------------
// Offset conv: 3x3 SAME, CB=256 -> 18 channels, input g_r, output g_off.
// ---------------------------------------------------------------------------
__global__ void offset_conv_kernel(const float* __restrict__ w_off,
                                   const float* __restrict__ b_off) {
    __shared__ float red[8][64][18];
    const int n  = blockIdx.y;
    const int p0 = blockIdx.x * 64;
    const int tid = threadIdx.x;
    const int g  = tid >> 5;   // 0..7
    const int lx = tid & 31;   // 0..31

    float acc[2][18];
#pragma unroll
    for (int q = 0; q < 2; ++q)
#pragma unroll
        for (int oc = 0; oc < 18; ++oc) acc[q][oc] = 0.f;

    for (int ci = g; ci < CB; ci += 8) {
        const float* rb = g_r + ((size_t)n * CB + ci) * HW;
        float v[2][9];
#pragma unroll
        for (int q = 0; q < 2; ++q) {
            int p = p0 + lx + q * 32;
            int h = p / Ww, w = p % Ww;
#pragma unroll
            for (int t = 0; t < 9; ++t) {
                int y = h + t / 3 - 1;
                int x = w + t % 3 - 1;
                v[q][t] = (y >= 0 && y < Hh && x >= 0 && x < Ww) ? rb[y * Ww + x] : 0.f;
            }
        }
        const float* wb = w_off + ci * 9;
#pragma unroll
        for (int oc = 0; oc < 18; ++oc) {
#pragma unroll
            for (int t = 0; t < 9; ++t) {
                float wv = wb[oc * (CB * 9) + t];  // broadcast within warp
                acc[0][oc] += wv * v[0][t];
                acc[1][oc] += wv * v[1][t];
            }
        }
    }

#pragma unroll
    for (int q = 0; q < 2; ++q)
#pragma unroll
        for (int oc = 0; oc < 18; ++oc)
            red[g][lx + q * 32][oc] = acc[q][oc];
    __syncthreads();

    for (int i = tid; i < 64 * 18; i += 256) {
        int ps = i / 18, oc = i % 18;
        float s = b_off[oc];
#pragma unroll
        for (int g2 = 0; g2 < 8; ++g2) s += red[g2][ps][oc];
        g_off[((size_t)n * 18 + oc) * HW + p0 + ps] = s;
    }
}

// ---------------------------------------------------------------------------
// Deformable 3x3 conv: implicit GEMM M=256(o), K=2304(c*9), 32 pixels/block.
// Block = 288 threads = 9 warps, one warp per tap, lane = pixel.
// Each thread keeps its 4 bilinear corner indices + weights IN REGISTERS for
// the entire channel loop (no idx/wt LDS traffic). Warps 0-7 also run the
// 4o x 8px FMA microtile; warp 8 is gather-only.
// ---------------------------------------------------------------------------
#define DP   32
#define CSTD 8

__global__ __launch_bounds__(288, 3) void deform_kernel(const float* __restrict__ b2) {
    __shared__ float s_val[CSTD][9][DP];

    const int blk = blockIdx.x;
    const int n  = blk / (HW / DP);
    const int pb = (blk % (HW / DP)) * DP;
    const int tid  = threadIdx.x;
    const int tap  = tid >> 5;   // 0..8
    const int lane = tid & 31;   // pixel within tile

    // --- per-thread bilinear corner state (registers) ---
    int   idx0, idx1, idx2, idx3;
    float wt0, wt1, wt2, wt3;
    {
        int p = pb + lane;
        int h = p / Ww, w = p % Ww;
        const float* offb = g_off + (size_t)n * 18 * HW + p;
        float dy = offb[(size_t)(tap * 2 + 0) * HW];
        float dx = offb[(size_t)(tap * 2 + 1) * HW];
        float ys = (float)(h + tap / 3 - 1) + dy;
        float xs = (float)(w + tap % 3 - 1) + dx;
        float y0f = floorf(ys), x0f = floorf(xs);
        float wy1 = ys - y0f, wy0 = 1.f - wy1;
        float wx1 = xs - x0f, wx0 = 1.f - wx1;
        int y0 = (int)y0f, x0 = (int)x0f;
        int y1 = y0 + 1, x1 = x0 + 1;
        bool vy0 = (y0 >= 0) && (y0 < Hh);
        bool vy1 = (y1 >= 0) && (y1 < Hh);
        bool vx0 = (x0 >= 0) && (x0 < Ww);
        bool vx1 = (x1 >= 0) && (x1 < Ww);
        int yc0 = min(max(y0, 0), Hh - 1), yc1 = min(max(y1, 0), Hh - 1);
        int xc0 = min(max(x0, 0), Ww - 1), xc1 = min(max(x1, 0), Ww - 1);
        idx0 = yc0 * Ww + xc0;  wt0 = (vy0 && vx0) ? wy0 * wx0 : 0.f;
        idx1 = yc0 * Ww + xc1;  wt1 = (vy0 && vx1) ? wy0 * wx1 : 0.f;
        idx2 = yc1 * Ww + xc0;  wt2 = (vy1 && vx0) ? wy1 * wx0 : 0.f;
        idx3 = yc1 * Ww + xc1;  wt3 = (vy1 && vx1) ? wy1 * wx1 : 0.f;
    }

    float acc[4][8] = {};
    const int oq  = tid >> 2;      // 0..63 -> o quad (valid when tid<256)
    const int px0 = (tid & 3) << 3;

    const float* fbase = g_r + (size_t)n * CB * HW;

    for (int cb = 0; cb < CB; cb += CSTD) {
        // --- gather phase: all 9 warps ---
#pragma unroll
        for (int cc = 0; cc < CSTD; ++cc) {
            const float* f = fbase + (size_t)(cb + cc) * HW;
            float v = wt0 * __ldg(f + idx0)
                    + wt1 * __ldg(f + idx1)
                    + wt2 * __ldg(f + idx2)
                    + wt3 * __ldg(f + idx3);
            s_val[cc][tap][lane] = v;
        }
        __syncthreads();

        // --- compute phase: warps 0..7 ---
        if (tid < 256) {
#pragma unroll
            for (int cc = 0; cc < CSTD; ++cc) {
                const float4* wrow =
                    (const float4*)(g_w2t + (size_t)(cb + cc) * (9 * CB));
#pragma unroll
                for (int t = 0; t < 9; ++t) {
                    float4 wv = wrow[t * 64 + oq];
                    float4 sa = *(const float4*)&s_val[cc][t][px0];
                    float4 sb = *(const float4*)&s_val[cc][t][px0 + 4];
                    float sv[8] = {sa.x, sa.y, sa.z, sa.w, sb.x, sb.y, sb.z, sb.w};
                    float wr[4] = {wv.x, wv.y, wv.z, wv.w};
#pragma unroll
                    for (int i = 0; i < 4; ++i)
#pragma unroll
                        for (int j = 0; j < 8; ++j)
                            acc[i][j] += wr[i] * sv[j];
                }
            }
        }
        __syncthreads();
    }

    if (tid < 256) {
#pragma unroll
        for (int i = 0; i < 4; ++i) {
            int o = (oq << 2) + i;
            float bb = b2[o];
            float* orow = g_r2 + ((size_t)n * CB + o) * HW + pb + px0;
            float4 o0, o1;
            o0.x = fmaxf(acc[i][0] + bb, 0.f);
            o0.y = fmaxf(acc[i][1] + bb, 0.f);
            o0.z = fmaxf(acc[i][2] + bb, 0.f);
            o0.w = fmaxf(acc[i][3] + bb, 0.f);
            o1.x = fmaxf(acc[i][4] + bb, 0.f);
            o1.y = fmaxf(acc[i][5] + bb, 0.f);
            o1.z = fmaxf(acc[i][6] + bb, 0.f);
            o1.w = fmaxf(acc[i][7] + bb, 0.f);
            *(float4*)orow       = o0;
            *(float4*)(orow + 4) = o1;
        }
    }
}

// ---------------------------------------------------------------------------
extern "C" void kernel_launch(void* const* d_in, const int* in_sizes, int n_in,
                              void* d_out, int out_size) {
    const float* x     = (const float*)d_in[0];
    const float* w1    = (const float*)d_in[1];
    const float* b1    = (const float*)d_in[2];
    const float* w_off = (const float*)d_in[3];
    const float* b_off = (const float*)d_in[4];
    const float* w2    = (const float*)d_in[5];
    const float* b2    = (const float*)d_in[6];
    const float* w3    = (const float*)d_in[7];
    const float* b3    = (const float*)d_in[8];
    float* out = (float*)d_out;

    float *r_ptr, *r2_ptr;
    cudaGetSymbolAddress((void**)&r_ptr, g_r);
    cudaGetSymbolAddress((void**)&r2_ptr, g_r2);

    // w2 transpose (independent of data path; cheap)
    transpose_w2_kernel<<<(CB * KT * CB + 255) / 256, 256>>>(w2);

    // conv1: 1024 -> 256, relu
    conv1x1_kernel<<<dim3(HW / BN, CB / BM, Nn), 256>>>(w1, x, b1, nullptr, r_ptr,
                                                        CB, CIN);

    // offset conv 3x3: 256 -> 18
    offset_conv_kernel<<<dim3(HW / 64, Nn), 256>>>(w_off, b_off);

    // deformable conv 3x3: 256 -> 256, relu
    deform_kernel<<<Nn * (HW / DP), 288>>>(b2);

    // conv3: 256 -> 1024 + x residual, relu
    conv1x1_kernel<<<dim3(HW / BN, CIN / BM, Nn), 256>>>(w3, r2_ptr, b3, x, out,
                                                         CIN, CB);
}

// round 4
// speedup vs baseline: 1.3015x; 1.2257x over previous
#include <cuda_runtime.h>
#include <cuda_bf16.h>
#include <math.h>
#include <stdint.h>

#define Nn   4
#define CIN  1024
#define CB   256
#define Hh   56
#define Ww   56
#define HW   3136
#define KT   9

// Scratch (device globals: allocation-free rule)
__device__ float g_r  [Nn * CB * HW];     // conv1 output (relu)
__device__ float g_off[Nn * 2 * KT * HW]; // offset conv output
__device__ float g_r2 [Nn * CB * HW];     // deform conv output (relu)
__device__ float g_w2t[CB * KT * CB];     // w2 transposed to [c*9+tap][o]

// ---------------------------------------------------------------------------
// split fp32 pair -> packed bf16x2 hi & lo (x in low half, y in high half)
// ---------------------------------------------------------------------------
__device__ __forceinline__ void split2(float x, float y, uint32_t& hi, uint32_t& lo) {
    __nv_bfloat16 xh = __float2bfloat16(x);
    __nv_bfloat16 yh = __float2bfloat16(y);
    __nv_bfloat16 xl = __float2bfloat16(x - __bfloat162float(xh));
    __nv_bfloat16 yl = __float2bfloat16(y - __bfloat162float(yh));
    hi = ((uint32_t)__bfloat16_as_ushort(yh) << 16) | __bfloat16_as_ushort(xh);
    lo = ((uint32_t)__bfloat16_as_ushort(yl) << 16) | __bfloat16_as_ushort(xl);
}
__device__ __forceinline__ void split8(const float4& a, const float4& b,
                                       uint4& hi, uint4& lo) {
    split2(a.x, a.y, hi.x, lo.x);
    split2(a.z, a.w, hi.y, lo.y);
    split2(b.x, b.y, hi.z, lo.z);
    split2(b.z, b.w, hi.w, lo.w);
}

__device__ __forceinline__ void mma16816(float* c, const uint32_t* a, const uint32_t* b) {
    asm volatile(
        "mma.sync.aligned.m16n8k16.row.col.f32.bf16.bf16.f32 "
        "{%0,%1,%2,%3}, {%4,%5,%6,%7}, {%8,%9}, {%0,%1,%2,%3};"
        : "+f"(c[0]), "+f"(c[1]), "+f"(c[2]), "+f"(c[3])
        : "r"(a[0]), "r"(a[1]), "r"(a[2]), "r"(a[3]), "r"(b[0]), "r"(b[1]));
}

// ---------------------------------------------------------------------------
// w2 (o,c,kh,kw) -> g_w2t[(c*9+tap)*256 + o]
// ---------------------------------------------------------------------------
__global__ void transpose_w2_kernel(const float* __restrict__ w2) {
    int i = blockIdx.x * 256 + threadIdx.x;
    if (i < CB * KT * CB) {
        int k = i / CB;
        int o = i % CB;
        int c = k / KT;
        int t = k % KT;
        g_w2t[i] = w2[(o * CB + c) * KT + t];
    }
}

// ===========================================================================
// Tensor-core (HMMA mma.sync) GEMM for the 1x1 convs.
// D[M,N] = A[M,K] * B[K,N] per image; 2-term bf16 split (AhBh + AhBl + AlBh).
// Tile: BM=128, BN=64 px, BK=32. 8 warps as 2(m) x 4(n); each warp 64x16
// via 4 m-frags x 2 n-frags of m16n8k16.
// A: weights, k-contiguous smem [128][40] (80B pitch -> conflict-free frags).
// B: activations, register-transposed to [px][k] smem [64][40].
// Epilogue: bias (+resid) + relu, fp32 out [M][HW].
// ===========================================================================
#define BKP 40  // padded K pitch (elements)

__global__ __launch_bounds__(256) void gemm_tc_kernel(
        const float* __restrict__ A,      // [M][Kd]
        const float* __restrict__ Bx,     // [Nn][Kd][HW]
        const float* __restrict__ bias,   // [M]
        const float* __restrict__ resid,  // [Nn][M][HW] or null
        float* __restrict__ C,            // [Nn][M][HW]
        int M, int Kd) {
    __shared__ __nv_bfloat16 As_hi[128][BKP];
    __shared__ __nv_bfloat16 As_lo[128][BKP];
    __shared__ __nv_bfloat16 Bs_hi[64][BKP];
    __shared__ __nv_bfloat16 Bs_lo[64][BKP];

    const int n  = blockIdx.z;
    const int m0 = blockIdx.y * 128;
    const int p0 = blockIdx.x * 64;
    const int tid = threadIdx.x;
    const int wid = tid >> 5;
    const int lid = tid & 31;
    const int q = lid >> 2;   // group id 0..7
    const int r = lid & 3;    // thread in group
    const int warp_m = wid >> 2;   // 0..1
    const int warp_n = wid & 3;    // 0..3
    const float* Bn = Bx + (size_t)n * Kd * HW;

    // A-load task: 2 tasks/thread, each = one row x 8 k
    const int a_row0 = tid >> 2;             // task0 row (0..63)
    const int a_kg   = (tid & 3) * 8;        // k offset 0,8,16,24
    // B-load task: 1 task/thread: kpair x 4px
    const int b_k   = (tid & 15) * 2;        // 0..30
    const int b_px  = (tid >> 4) * 4;        // 0..60

    float acc[4][2][4] = {};  // [mf][nf][4]

    const int KC = Kd >> 5;   // chunks of 32

    // global prefetch regs
    float4 ga[2][2], gb[2];
    {
        const float* g0 = A + (size_t)(m0 + a_row0) * Kd + a_kg;
        ga[0][0] = *(const float4*)g0;
        ga[0][1] = *(const float4*)(g0 + 4);
        const float* g1 = A + (size_t)(m0 + a_row0 + 64) * Kd + a_kg;
        ga[1][0] = *(const float4*)g1;
        ga[1][1] = *(const float4*)(g1 + 4);
        const float* gB = Bn + (size_t)b_k * HW + p0 + b_px;
        gb[0] = *(const float4*)gB;
        gb[1] = *(const float4*)(gB + HW);
    }

    for (int kc = 0; kc < KC; ++kc) {
        __syncthreads();  // smem free (previous compute done)
        // store A tiles
#pragma unroll
        for (int t = 0; t < 2; ++t) {
            int row = a_row0 + t * 64;
            uint4 hi, lo;
            split8(ga[t][0], ga[t][1], hi, lo);
            *(uint4*)&As_hi[row][a_kg] = hi;
            *(uint4*)&As_lo[row][a_kg] = lo;
        }
        // store B tiles (register transpose k<->px)
        {
            float vk[4]  = {gb[0].x, gb[0].y, gb[0].z, gb[0].w};
            float vk1[4] = {gb[1].x, gb[1].y, gb[1].z, gb[1].w};
#pragma unroll
            for (int j = 0; j < 4; ++j) {
                uint32_t hi, lo;
                split2(vk[j], vk1[j], hi, lo);
                *(uint32_t*)&Bs_hi[b_px + j][b_k] = hi;
                *(uint32_t*)&Bs_lo[b_px + j][b_k] = lo;
            }
        }
        __syncthreads();

        // prefetch next chunk
        if (kc + 1 < KC) {
            const int k0 = (kc + 1) << 5;
            const float* g0 = A + (size_t)(m0 + a_row0) * Kd + k0 + a_kg;
            ga[0][0] = *(const float4*)g0;
            ga[0][1] = *(const float4*)(g0 + 4);
            const float* g1 = A + (size_t)(m0 + a_row0 + 64) * Kd + k0 + a_kg;
            ga[1][0] = *(const float4*)g1;
            ga[1][1] = *(const float4*)(g1 + 4);
            const float* gB = Bn + (size_t)(k0 + b_k) * HW + p0 + b_px;
            gb[0] = *(const float4*)gB;
            gb[1] = *(const float4*)(gB + HW);
        }

        // compute: 2 k16 steps
#pragma unroll
        for (int ks = 0; ks < 32; ks += 16) {
            uint32_t bf_hi[2][2], bf_lo[2][2];
#pragma unroll
            for (int nf = 0; nf < 2; ++nf) {
                int nn = warp_n * 16 + nf * 8 + q;
                bf_hi[nf][0] = *(const uint32_t*)&Bs_hi[nn][ks + 2 * r];
                bf_hi[nf][1] = *(const uint32_t*)&Bs_hi[nn][ks + 2 * r + 8];
                bf_lo[nf][0] = *(const uint32_t*)&Bs_lo[nn][ks + 2 * r];
                bf_lo[nf][1] = *(const uint32_t*)&Bs_lo[nn][ks + 2 * r + 8];
            }
#pragma unroll
            for (int mf = 0; mf < 4; ++mf) {
                int mb = warp_m * 64 + mf * 16;
                uint32_t ah[4], al[4];
                ah[0] = *(const uint32_t*)&As_hi[mb + q][ks + 2 * r];
                ah[1] = *(const uint32_t*)&As_hi[mb + q + 8][ks + 2 * r];
                ah[2] = *(const uint32_t*)&As_hi[mb + q][ks + 2 * r + 8];
                ah[3] = *(const uint32_t*)&As_hi[mb + q + 8][ks + 2 * r + 8];
                al[0] = *(const uint32_t*)&As_lo[mb + q][ks + 2 * r];
                al[1] = *(const uint32_t*)&As_lo[mb + q + 8][ks + 2 * r];
                al[2] = *(const uint32_t*)&As_lo[mb + q][ks + 2 * r + 8];
                al[3] = *(const uint32_t*)&As_lo[mb + q + 8][ks + 2 * r + 8];
#pragma unroll
                for (int nf = 0; nf < 2; ++nf) {
                    mma16816(acc[mf][nf], ah, bf_hi[nf]);
                    mma16816(acc[mf][nf], ah, bf_lo[nf]);
                    mma16816(acc[mf][nf], al, bf_hi[nf]);
                }
            }
        }
    }

    // epilogue
#pragma unroll
    for (int mf = 0; mf < 4; ++mf) {
#pragma unroll
        for (int nf = 0; nf < 2; ++nf) {
            int m  = m0 + warp_m * 64 + mf * 16 + q;
            int px = p0 + warp_n * 16 + nf * 8 + 2 * r;
#pragma unroll
            for (int half = 0; half < 2; ++half) {
                int mm = m + half * 8;
                float c0 = acc[mf][nf][half * 2 + 0];
                float c1 = acc[mf][nf][half * 2 + 1];
                float bb = bias[mm];
                size_t base = ((size_t)n * M + mm) * HW + px;
                if (resid) {
                    float2 rv = *(const float2*)(resid + base);
                    c0 += rv.x;
                    c1 += rv.y;
                }
                float2 o;
                o.x = fmaxf(c0 + bb, 0.f);
                o.y = fmaxf(c1 + bb, 0.f);
                *(float2*)(C + base) = o;
            }
        }
    }
}

// ---------------------------------------------------------------------------
// Offset conv: 3x3 SAME, CB=256 -> 18 channels, input g_r, output g_off.
// ---------------------------------------------------------------------------
__global__ void offset_conv_kernel(const float* __restrict__ w_off,
                                   const float* __restrict__ b_off) {
    __shared__ float red[8][64][18];
    const int n  = blockIdx.y;
    const int p0 = blockIdx.x * 64;
    const int tid = threadIdx.x;
    const int g  = tid >> 5;
    const int lx = tid & 31;

    float acc[2][18];
#pragma unroll
    for (int qq = 0; qq < 2; ++qq)
#pragma unroll
        for (int oc = 0; oc < 18; ++oc) acc[qq][oc] = 0.f;

    for (int ci = g; ci < CB; ci += 8) {
        const float* rb = g_r + ((size_t)n * CB + ci) * HW;
        float v[2][9];
#pragma unroll
        for (int qq = 0; qq < 2; ++qq) {
            int p = p0 + lx + qq * 32;
            int h = p / Ww, w = p % Ww;
#pragma unroll
            for (int t = 0; t < 9; ++t) {
                int y = h + t / 3 - 1;
                int x = w + t % 3 - 1;
                v[qq][t] = (y >= 0 && y < Hh && x >= 0 && x < Ww) ? rb[y * Ww + x] : 0.f;
            }
        }
        const float* wb = w_off + ci * 9;
#pragma unroll
        for (int oc = 0; oc < 18; ++oc) {
#pragma unroll
            for (int t = 0; t < 9; ++t) {
                float wv = wb[oc * (CB * 9) + t];
                acc[0][oc] += wv * v[0][t];
                acc[1][oc] += wv * v[1][t];
            }
        }
    }

#pragma unroll
    for (int qq = 0; qq < 2; ++qq)
#pragma unroll
        for (int oc = 0; oc < 18; ++oc)
            red[g][lx + qq * 32][oc] = acc[qq][oc];
    __syncthreads();

    for (int i = tid; i < 64 * 18; i += 256) {
        int ps = i / 18, oc = i % 18;
        float s = b_off[oc];
#pragma unroll
        for (int g2 = 0; g2 < 8; ++g2) s += red[g2][ps][oc];
        g_off[((size_t)n * 18 + oc) * HW + p0 + ps] = s;
    }
}

// ---------------------------------------------------------------------------
// Deformable 3x3 conv (fp32): 32 px/block, 9 warps (one per tap)
// ---------------------------------------------------------------------------
#define DP   32
#define CSTD 8

__global__ __launch_bounds__(288, 3) void deform_kernel(const float* __restrict__ b2) {
    __shared__ float s_val[CSTD][9][DP];

    const int blk = blockIdx.x;
    const int n  = blk / (HW / DP);
    const int pb = (blk % (HW / DP)) * DP;
    const int tid  = threadIdx.x;
    const int tap  = tid >> 5;
    const int lane = tid & 31;

    int   idx0, idx1, idx2, idx3;
    float wt0, wt1, wt2, wt3;
    {
        int p = pb + lane;
        int h = p / Ww, w = p % Ww;
        const float* offb = g_off + (size_t)n * 18 * HW + p;
        float dy = offb[(size_t)(tap * 2 + 0) * HW];
        float dx = offb[(size_t)(tap * 2 + 1) * HW];
        float ys = (float)(h + tap / 3 - 1) + dy;
        float xs = (float)(w + tap % 3 - 1) + dx;
        float y0f = floorf(ys), x0f = floorf(xs);
        float wy1 = ys - y0f, wy0 = 1.f - wy1;
        float wx1 = xs - x0f, wx0 = 1.f - wx1;
        int y0 = (int)y0f, x0 = (int)x0f;
        int y1 = y0 + 1, x1 = x0 + 1;
        bool vy0 = (y0 >= 0) && (y0 < Hh);
        bool vy1 = (y1 >= 0) && (y1 < Hh);
        bool vx0 = (x0 >= 0) && (x0 < Ww);
        bool vx1 = (x1 >= 0) && (x1 < Ww);
        int yc0 = min(max(y0, 0), Hh - 1), yc1 = min(max(y1, 0), Hh - 1);
        int xc0 = min(max(x0, 0), Ww - 1), xc1 = min(max(x1, 0), Ww - 1);
        idx0 = yc0 * Ww + xc0;  wt0 = (vy0 && vx0) ? wy0 * wx0 : 0.f;
        idx1 = yc0 * Ww + xc1;  wt1 = (vy0 && vx1) ? wy0 * wx1 : 0.f;
        idx2 = yc1 * Ww + xc0;  wt2 = (vy1 && vx0) ? wy1 * wx0 : 0.f;
        idx3 = yc1 * Ww + xc1;  wt3 = (vy1 && vx1) ? wy1 * wx1 : 0.f;
    }

    float acc[4][8] = {};
    const int oq  = tid >> 2;
    const int px0 = (tid & 3) << 3;

    const float* fbase = g_r + (size_t)n * CB * HW;

    for (int cb = 0; cb < CB; cb += CSTD) {
#pragma unroll
        for (int cc = 0; cc < CSTD; ++cc) {
            const float* f = fbase + (size_t)(cb + cc) * HW;
            float v = wt0 * __ldg(f + idx0)
                    + wt1 * __ldg(f + idx1)
                    + wt2 * __ldg(f + idx2)
                    + wt3 * __ldg(f + idx3);
            s_val[cc][tap][lane] = v;
        }
        __syncthreads();

        if (tid < 256) {
#pragma unroll
            for (int cc = 0; cc < CSTD; ++cc) {
                const float4* wrow =
                    (const float4*)(g_w2t + (size_t)(cb + cc) * (9 * CB));
#pragma unroll
                for (int t = 0; t < 9; ++t) {
                    float4 wv = wrow[t * 64 + oq];
                    float4 sa = *(const float4*)&s_val[cc][t][px0];
                    float4 sb = *(const float4*)&s_val[cc][t][px0 + 4];
                    float sv[8] = {sa.x, sa.y, sa.z, sa.w, sb.x, sb.y, sb.z, sb.w};
                    float wr[4] = {wv.x, wv.y, wv.z, wv.w};
#pragma unroll
                    for (int i = 0; i < 4; ++i)
#pragma unroll
                        for (int j = 0; j < 8; ++j)
                            acc[i][j] += wr[i] * sv[j];
                }
            }
        }
        __syncthreads();
    }

    if (tid < 256) {
#pragma unroll
        for (int i = 0; i < 4; ++i) {
            int o = (oq << 2) + i;
            float bb = b2[o];
            float* orow = g_r2 + ((size_t)n * CB + o) * HW + pb + px0;
            float4 o0, o1;
            o0.x = fmaxf(acc[i][0] + bb, 0.f);
            o0.y = fmaxf(acc[i][1] + bb, 0.f);
            o0.z = fmaxf(acc[i][2] + bb, 0.f);
            o0.w = fmaxf(acc[i][3] + bb, 0.f);
            o1.x = fmaxf(acc[i][4] + bb, 0.f);
            o1.y = fmaxf(acc[i][5] + bb, 0.f);
            o1.z = fmaxf(acc[i][6] + bb, 0.f);
            o1.w = fmaxf(acc[i][7] + bb, 0.f);
            *(float4*)orow       = o0;
            *(float4*)(orow + 4) = o1;
        }
    }
}

// ---------------------------------------------------------------------------
extern "C" void kernel_launch(void* const* d_in, const int* in_sizes, int n_in,
                              void* d_out, int out_size) {
    const float* x     = (const float*)d_in[0];
    const float* w1    = (const float*)d_in[1];
    const float* b1    = (const float*)d_in[2];
    const float* w_off = (const float*)d_in[3];
    const float* b_off = (const float*)d_in[4];
    const float* w2    = (const float*)d_in[5];
    const float* b2    = (const float*)d_in[6];
    const float* w3    = (const float*)d_in[7];
    const float* b3    = (const float*)d_in[8];
    float* out = (float*)d_out;

    float *r_ptr, *r2_ptr;
    cudaGetSymbolAddress((void**)&r_ptr, g_r);
    cudaGetSymbolAddress((void**)&r2_ptr, g_r2);

    transpose_w2_kernel<<<(CB * KT * CB + 255) / 256, 256>>>(w2);

    // conv1: 1024 -> 256, relu (HMMA split-bf16)
    gemm_tc_kernel<<<dim3(HW / 64, CB / 128, Nn), 256>>>(
        w1, x, b1, nullptr, r_ptr, CB, CIN);

    // offset conv 3x3: 256 -> 18
    offset_conv_kernel<<<dim3(HW / 64, Nn), 256>>>(w_off, b_off);

    // deformable conv 3x3: 256 -> 256, relu
    deform_kernel<<<Nn * (HW / DP), 288>>>(b2);

    // conv3: 256 -> 1024 + x residual, relu (HMMA split-bf16)
    gemm_tc_kernel<<<dim3(HW / 64, CIN / 128, Nn), 256>>>(
        w3, r2_ptr, b3, x, out, CIN, CB);
}

// round 5
// speedup vs baseline: 1.6372x; 1.2579x over previous
#include <cuda_runtime.h>
#include <cuda_bf16.h>
#include <math.h>
#include <stdint.h>

#define Nn   4
#define CIN  1024
#define CB   256
#define Hh   56
#define Ww   56
#define HW   3136
#define KT   9
#define KD   (CB * KT)   // 2304

// Scratch (device globals: allocation-free rule)
__device__ float g_r  [Nn * CB * HW];     // conv1 output (relu)
__device__ float g_off[Nn * 2 * KT * HW]; // offset conv output
__device__ float g_r2 [Nn * CB * HW];     // deform conv output (relu)
__device__ __nv_bfloat16 g_w2h[CB * KD];  // w2 split hi, [o][tap*256+c]
__device__ __nv_bfloat16 g_w2l[CB * KD];  // w2 split lo

// ---------------------------------------------------------------------------
// split fp32 pair -> packed bf16x2 hi & lo (x in low half, y in high half)
// ---------------------------------------------------------------------------
__device__ __forceinline__ void split2(float x, float y, uint32_t& hi, uint32_t& lo) {
    __nv_bfloat16 xh = __float2bfloat16(x);
    __nv_bfloat16 yh = __float2bfloat16(y);
    __nv_bfloat16 xl = __float2bfloat16(x - __bfloat162float(xh));
    __nv_bfloat16 yl = __float2bfloat16(y - __bfloat162float(yh));
    hi = ((uint32_t)__bfloat16_as_ushort(yh) << 16) | __bfloat16_as_ushort(xh);
    lo = ((uint32_t)__bfloat16_as_ushort(yl) << 16) | __bfloat16_as_ushort(xl);
}
__device__ __forceinline__ void split8(const float4& a, const float4& b,
                                       uint4& hi, uint4& lo) {
    split2(a.x, a.y, hi.x, lo.x);
    split2(a.z, a.w, hi.y, lo.y);
    split2(b.x, b.y, hi.z, lo.z);
    split2(b.z, b.w, hi.w, lo.w);
}

__device__ __forceinline__ void mma16816(float* c, const uint32_t* a, const uint32_t* b) {
    asm volatile(
        "mma.sync.aligned.m16n8k16.row.col.f32.bf16.bf16.f32 "
        "{%0,%1,%2,%3}, {%4,%5,%6,%7}, {%8,%9}, {%0,%1,%2,%3};"
        : "+f"(c[0]), "+f"(c[1]), "+f"(c[2]), "+f"(c[3])
        : "r"(a[0]), "r"(a[1]), "r"(a[2]), "r"(a[3]), "r"(b[0]), "r"(b[1]));
}

// ---------------------------------------------------------------------------
// w2 (o,c,kh,kw) fp32 -> bf16 hi/lo at [o][tap*256+c]
// ---------------------------------------------------------------------------
__global__ void prep_w2_kernel(const float* __restrict__ w2) {
    int i = blockIdx.x * 256 + threadIdx.x;
    if (i < CB * KD) {
        int o = i / KD;
        int k = i % KD;
        int tap = k >> 8;
        int c   = k & 255;
        float v = w2[(o * CB + c) * KT + tap];
        __nv_bfloat16 h = __float2bfloat16(v);
        g_w2h[i] = h;
        g_w2l[i] = __float2bfloat16(v - __bfloat162float(h));
    }
}

// ===========================================================================
// Tensor-core (HMMA) GEMM for the 1x1 convs (unchanged from R4).
// ===========================================================================
#define BKP 40

__global__ __launch_bounds__(256) void gemm_tc_kernel(
        const float* __restrict__ A, const float* __restrict__ Bx,
        const float* __restrict__ bias, const float* __restrict__ resid,
        float* __restrict__ C, int M, int Kd) {
    __shared__ __nv_bfloat16 As_hi[128][BKP];
    __shared__ __nv_bfloat16 As_lo[128][BKP];
    __shared__ __nv_bfloat16 Bs_hi[64][BKP];
    __shared__ __nv_bfloat16 Bs_lo[64][BKP];

    const int n  = blockIdx.z;
    const int m0 = blockIdx.y * 128;
    const int p0 = blockIdx.x * 64;
    const int tid = threadIdx.x;
    const int wid = tid >> 5;
    const int lid = tid & 31;
    const int q = lid >> 2;
    const int r = lid & 3;
    const int warp_m = wid >> 2;
    const int warp_n = wid & 3;
    const float* Bn = Bx + (size_t)n * Kd * HW;

    const int a_row0 = tid >> 2;
    const int a_kg   = (tid & 3) * 8;
    const int b_k   = (tid & 15) * 2;
    const int b_px  = (tid >> 4) * 4;

    float acc[4][2][4] = {};
    const int KC = Kd >> 5;

    float4 ga[2][2], gb[2];
    {
        const float* g0 = A + (size_t)(m0 + a_row0) * Kd + a_kg;
        ga[0][0] = *(const float4*)g0;
        ga[0][1] = *(const float4*)(g0 + 4);
        const float* g1 = A + (size_t)(m0 + a_row0 + 64) * Kd + a_kg;
        ga[1][0] = *(const float4*)g1;
        ga[1][1] = *(const float4*)(g1 + 4);
        const float* gB = Bn + (size_t)b_k * HW + p0 + b_px;
        gb[0] = *(const float4*)gB;
        gb[1] = *(const float4*)(gB + HW);
    }

    for (int kc = 0; kc < KC; ++kc) {
        __syncthreads();
#pragma unroll
        for (int t = 0; t < 2; ++t) {
            int row = a_row0 + t * 64;
            uint4 hi, lo;
            split8(ga[t][0], ga[t][1], hi, lo);
            *(uint4*)&As_hi[row][a_kg] = hi;
            *(uint4*)&As_lo[row][a_kg] = lo;
        }
        {
            float vk[4]  = {gb[0].x, gb[0].y, gb[0].z, gb[0].w};
            float vk1[4] = {gb[1].x, gb[1].y, gb[1].z, gb[1].w};
#pragma unroll
            for (int j = 0; j < 4; ++j) {
                uint32_t hi, lo;
                split2(vk[j], vk1[j], hi, lo);
                *(uint32_t*)&Bs_hi[b_px + j][b_k] = hi;
                *(uint32_t*)&Bs_lo[b_px + j][b_k] = lo;
            }
        }
        __syncthreads();

        if (kc + 1 < KC) {
            const int k0 = (kc + 1) << 5;
            const float* g0 = A + (size_t)(m0 + a_row0) * Kd + k0 + a_kg;
            ga[0][0] = *(const float4*)g0;
            ga[0][1] = *(const float4*)(g0 + 4);
            const float* g1 = A + (size_t)(m0 + a_row0 + 64) * Kd + k0 + a_kg;
            ga[1][0] = *(const float4*)g1;
            ga[1][1] = *(const float4*)(g1 + 4);
            const float* gB = Bn + (size_t)(k0 + b_k) * HW + p0 + b_px;
            gb[0] = *(const float4*)gB;
            gb[1] = *(const float4*)(gB + HW);
        }

#pragma unroll
        for (int ks = 0; ks < 32; ks += 16) {
            uint32_t bf_hi[2][2], bf_lo[2][2];
#pragma unroll
            for (int nf = 0; nf < 2; ++nf) {
                int nn = warp_n * 16 + nf * 8 + q;
                bf_hi[nf][0] = *(const uint32_t*)&Bs_hi[nn][ks + 2 * r];
                bf_hi[nf][1] = *(const uint32_t*)&Bs_hi[nn][ks + 2 * r + 8];
                bf_lo[nf][0] = *(const uint32_t*)&Bs_lo[nn][ks + 2 * r];
                bf_lo[nf][1] = *(const uint32_t*)&Bs_lo[nn][ks + 2 * r + 8];
            }
#pragma unroll
            for (int mf = 0; mf < 4; ++mf) {
                int mb = warp_m * 64 + mf * 16;
                uint32_t ah[4], al[4];
                ah[0] = *(const uint32_t*)&As_hi[mb + q][ks + 2 * r];
                ah[1] = *(const uint32_t*)&As_hi[mb + q + 8][ks + 2 * r];
                ah[2] = *(const uint32_t*)&As_hi[mb + q][ks + 2 * r + 8];
                ah[3] = *(const uint32_t*)&As_hi[mb + q + 8][ks + 2 * r + 8];
                al[0] = *(const uint32_t*)&As_lo[mb + q][ks + 2 * r];
                al[1] = *(const uint32_t*)&As_lo[mb + q + 8][ks + 2 * r];
                al[2] = *(const uint32_t*)&As_lo[mb + q][ks + 2 * r + 8];
                al[3] = *(const uint32_t*)&As_lo[mb + q + 8][ks + 2 * r + 8];
#pragma unroll
                for (int nf = 0; nf < 2; ++nf) {
                    mma16816(acc[mf][nf], ah, bf_hi[nf]);
                    mma16816(acc[mf][nf], ah, bf_lo[nf]);
                    mma16816(acc[mf][nf], al, bf_hi[nf]);
                }
            }
        }
    }

#pragma unroll
    for (int mf = 0; mf < 4; ++mf) {
#pragma unroll
        for (int nf = 0; nf < 2; ++nf) {
            int m  = m0 + warp_m * 64 + mf * 16 + q;
            int px = p0 + warp_n * 16 + nf * 8 + 2 * r;
#pragma unroll
            for (int half = 0; half < 2; ++half) {
                int mm = m + half * 8;
                float c0 = acc[mf][nf][half * 2 + 0];
                float c1 = acc[mf][nf][half * 2 + 1];
                float bb = bias[mm];
                size_t base = ((size_t)n * M + mm) * HW + px;
                if (resid) {
                    float2 rv = *(const float2*)(resid + base);
                    c0 += rv.x;
                    c1 += rv.y;
                }
                float2 o;
                o.x = fmaxf(c0 + bb, 0.f);
                o.y = fmaxf(c1 + bb, 0.f);
                *(float2*)(C + base) = o;
            }
        }
    }
}

// ---------------------------------------------------------------------------
// Offset conv: 3x3 SAME, CB=256 -> 18 channels (unchanged)
// ---------------------------------------------------------------------------
__global__ void offset_conv_kernel(const float* __restrict__ w_off,
                                   const float* __restrict__ b_off) {
    __shared__ float red[8][64][18];
    const int n  = blockIdx.y;
    const int p0 = blockIdx.x * 64;
    const int tid = threadIdx.x;
    const int g  = tid >> 5;
    const int lx = tid & 31;

    float acc[2][18];
#pragma unroll
    for (int qq = 0; qq < 2; ++qq)
#pragma unroll
        for (int oc = 0; oc < 18; ++oc) acc[qq][oc] = 0.f;

    for (int ci = g; ci < CB; ci += 8) {
        const float* rb = g_r + ((size_t)n * CB + ci) * HW;
        float v[2][9];
#pragma unroll
        for (int qq = 0; qq < 2; ++qq) {
            int p = p0 + lx + qq * 32;
            int h = p / Ww, w = p % Ww;
#pragma unroll
            for (int t = 0; t < 9; ++t) {
                int y = h + t / 3 - 1;
                int x = w + t % 3 - 1;
                v[qq][t] = (y >= 0 && y < Hh && x >= 0 && x < Ww) ? rb[y * Ww + x] : 0.f;
            }
        }
        const float* wb = w_off + ci * 9;
#pragma unroll
        for (int oc = 0; oc < 18; ++oc) {
#pragma unroll
            for (int t = 0; t < 9; ++t) {
                float wv = wb[oc * (CB * 9) + t];
                acc[0][oc] += wv * v[0][t];
                acc[1][oc] += wv * v[1][t];
            }
        }
    }

#pragma unroll
    for (int qq = 0; qq < 2; ++qq)
#pragma unroll
        for (int oc = 0; oc < 18; ++oc)
            red[g][lx + qq * 32][oc] = acc[qq][oc];
    __syncthreads();

    for (int i = tid; i < 64 * 18; i += 256) {
        int ps = i / 18, oc = i % 18;
        float s = b_off[oc];
#pragma unroll
        for (int g2 = 0; g2 < 8; ++g2) s += red[g2][ps][oc];
        g_off[((size_t)n * 18 + oc) * HW + p0 + ps] = s;
    }
}

// ===========================================================================
// Deformable 3x3 conv on tensor cores.
// Implicit GEMM: out[o][px] = sum_k w2[o][k] * s[k][px], k = tap*256 + c.
// Block: 256 thr, 64 px (N), 128 o (M, 2 halves via blockIdx.y), K-chunk=64.
// Gather: all threads, bilinear state in regs (recomputed per tap), output
// packed bf16 hi/lo -> Bs [px][k]. Weights staged per chunk -> As [o][k].
// MMA: 8 warps = 4(m)x2(n), m16n8k16, 3-term split.
// ===========================================================================
#define DPITCH 72
#define DSM_AS_H 0
#define DSM_AS_L 18432
#define DSM_BS_H 36864
#define DSM_BS_L 46080
#define DSM_BYTES 55296

__global__ __launch_bounds__(256, 2) void deform_mma_kernel(const float* __restrict__ b2) {
    extern __shared__ char dsm[];
    __nv_bfloat16 (*As_h)[DPITCH] = (__nv_bfloat16(*)[DPITCH])(dsm + DSM_AS_H);
    __nv_bfloat16 (*As_l)[DPITCH] = (__nv_bfloat16(*)[DPITCH])(dsm + DSM_AS_L);
    __nv_bfloat16 (*Bs_h)[DPITCH] = (__nv_bfloat16(*)[DPITCH])(dsm + DSM_BS_H);
    __nv_bfloat16 (*Bs_l)[DPITCH] = (__nv_bfloat16(*)[DPITCH])(dsm + DSM_BS_L);

    const int pb = blockIdx.x * 64;
    const int m0 = blockIdx.y * 128;
    const int n  = blockIdx.z;
    const int tid = threadIdx.x;
    const int wid = tid >> 5;
    const int lid = tid & 31;
    const int q = lid >> 2;
    const int r = lid & 3;
    const int wm = wid & 3;     // m warp: 32 rows
    const int wn = wid >> 2;    // n warp: 32 px

    // gather role
    const int gpx = tid & 63;
    const int gg  = tid >> 6;   // 0..3 -> 16 channels each

    const float* fbase = g_r + (size_t)n * CB * HW;

    float acc[2][4][4] = {};    // [mf][nf][4]

    for (int tap = 0; tap < 9; ++tap) {
        // bilinear state for (tap, gpx) in registers
        int   idx0, idx1, idx2, idx3;
        float wt0, wt1, wt2, wt3;
        {
            int p = pb + gpx;
            int h = p / Ww, w = p % Ww;
            const float* offb = g_off + (size_t)n * 18 * HW + p;
            float dy = offb[(size_t)(tap * 2 + 0) * HW];
            float dx = offb[(size_t)(tap * 2 + 1) * HW];
            float ys = (float)(h + tap / 3 - 1) + dy;
            float xs = (float)(w + tap % 3 - 1) + dx;
            float y0f = floorf(ys), x0f = floorf(xs);
            float wy1 = ys - y0f, wy0 = 1.f - wy1;
            float wx1 = xs - x0f, wx0 = 1.f - wx1;
            int y0 = (int)y0f, x0 = (int)x0f;
            int y1 = y0 + 1, x1 = x0 + 1;
            bool vy0 = (y0 >= 0) && (y0 < Hh);
            bool vy1 = (y1 >= 0) && (y1 < Hh);
            bool vx0 = (x0 >= 0) && (x0 < Ww);
            bool vx1 = (x1 >= 0) && (x1 < Ww);
            int yc0 = min(max(y0, 0), Hh - 1), yc1 = min(max(y1, 0), Hh - 1);
            int xc0 = min(max(x0, 0), Ww - 1), xc1 = min(max(x1, 0), Ww - 1);
            idx0 = yc0 * Ww + xc0;  wt0 = (vy0 && vx0) ? wy0 * wx0 : 0.f;
            idx1 = yc0 * Ww + xc1;  wt1 = (vy0 && vx1) ? wy0 * wx1 : 0.f;
            idx2 = yc1 * Ww + xc0;  wt2 = (vy1 && vx0) ? wy1 * wx0 : 0.f;
            idx3 = yc1 * Ww + xc1;  wt3 = (vy1 && vx1) ? wy1 * wx1 : 0.f;
        }

        for (int cq = 0; cq < 4; ++cq) {
            const int c0 = cq * 64;
            const int k0 = tap * 256 + c0;
            __syncthreads();  // smem free from previous MMA phase

            // --- stage weights: As[128][64] hi/lo ---
#pragma unroll
            for (int pass = 0; pass < 4; ++pass) {
                int id   = tid + pass * 256;     // 0..1023
                int row  = id >> 3;              // 0..127
                int quad = id & 7;               // 8 bf16 each
                size_t goff = (size_t)(m0 + row) * KD + k0 + quad * 8;
                uint4 h = *(const uint4*)(g_w2h + goff);
                uint4 l = *(const uint4*)(g_w2l + goff);
                *(uint4*)&As_h[row][quad * 8] = h;
                *(uint4*)&As_l[row][quad * 8] = l;
            }

            // --- gather: 16 channels x 1 px per thread ---
#pragma unroll
            for (int half = 0; half < 2; ++half) {
                float v[8];
#pragma unroll
                for (int j = 0; j < 8; ++j) {
                    int c = c0 + gg * 16 + half * 8 + j;
                    const float* f = fbase + (size_t)c * HW;
                    v[j] = wt0 * __ldg(f + idx0)
                         + wt1 * __ldg(f + idx1)
                         + wt2 * __ldg(f + idx2)
                         + wt3 * __ldg(f + idx3);
                }
                uint4 hi, lo;
                split2(v[0], v[1], hi.x, lo.x);
                split2(v[2], v[3], hi.y, lo.y);
                split2(v[4], v[5], hi.z, lo.z);
                split2(v[6], v[7], hi.w, lo.w);
                int cl = gg * 16 + half * 8;
                *(uint4*)&Bs_h[gpx][cl] = hi;
                *(uint4*)&Bs_l[gpx][cl] = lo;
            }
            __syncthreads();

            // --- MMA: 4 k16 steps over the 64-k chunk ---
#pragma unroll
            for (int ks = 0; ks < 64; ks += 16) {
                uint32_t bh[4][2], bl[4][2];
#pragma unroll
                for (int nf = 0; nf < 4; ++nf) {
                    int nn = wn * 32 + nf * 8 + q;
                    bh[nf][0] = *(const uint32_t*)&Bs_h[nn][ks + 2 * r];
                    bh[nf][1] = *(const uint32_t*)&Bs_h[nn][ks + 2 * r + 8];
                    bl[nf][0] = *(const uint32_t*)&Bs_l[nn][ks + 2 * r];
                    bl[nf][1] = *(const uint32_t*)&Bs_l[nn][ks + 2 * r + 8];
                }
#pragma unroll
                for (int mf = 0; mf < 2; ++mf) {
                    int mb = wm * 32 + mf * 16;
                    uint32_t ah[4], al[4];
                    ah[0] = *(const uint32_t*)&As_h[mb + q][ks + 2 * r];
                    ah[1] = *(const uint32_t*)&As_h[mb + q + 8][ks + 2 * r];
                    ah[2] = *(const uint32_t*)&As_h[mb + q][ks + 2 * r + 8];
                    ah[3] = *(const uint32_t*)&As_h[mb + q + 8][ks + 2 * r + 8];
                    al[0] = *(const uint32_t*)&As_l[mb + q][ks + 2 * r];
                    al[1] = *(const uint32_t*)&As_l[mb + q + 8][ks + 2 * r];
                    al[2] = *(const uint32_t*)&As_l[mb + q][ks + 2 * r + 8];
                    al[3] = *(const uint32_t*)&As_l[mb + q + 8][ks + 2 * r + 8];
#pragma unroll
                    for (int nf = 0; nf < 4; ++nf) {
                        mma16816(acc[mf][nf], ah, bh[nf]);
                        mma16816(acc[mf][nf], ah, bl[nf]);
                        mma16816(acc[mf][nf], al, bh[nf]);
                    }
                }
            }
        }
    }

    // epilogue: bias + relu -> g_r2
#pragma unroll
    for (int mf = 0; mf < 2; ++mf) {
#pragma unroll
        for (int half = 0; half < 2; ++half) {
            int o = m0 + wm * 32 + mf * 16 + q + half * 8;
            float bb = b2[o];
            float* orow = g_r2 + ((size_t)n * CB + o) * HW + pb;
#pragma unroll
            for (int nf = 0; nf < 4; ++nf) {
                int px = wn * 32 + nf * 8 + 2 * r;
                float2 ov;
                ov.x = fmaxf(acc[mf][nf][half * 2 + 0] + bb, 0.f);
                ov.y = fmaxf(acc[mf][nf][half * 2 + 1] + bb, 0.f);
                *(float2*)(orow + px) = ov;
            }
        }
    }
}

// ---------------------------------------------------------------------------
extern "C" void kernel_launch(void* const* d_in, const int* in_sizes, int n_in,
                              void* d_out, int out_size) {
    const float* x     = (const float*)d_in[0];
    const float* w1    = (const float*)d_in[1];
    const float* b1    = (const float*)d_in[2];
    const float* w_off = (const float*)d_in[3];
    const float* b_off = (const float*)d_in[4];
    const float* w2    = (const float*)d_in[5];
    const float* b2    = (const float*)d_in[6];
    const float* w3    = (const float*)d_in[7];
    const float* b3    = (const float*)d_in[8];
    float* out = (float*)d_out;

    float *r_ptr, *r2_ptr;
    cudaGetSymbolAddress((void**)&r_ptr, g_r);
    cudaGetSymbolAddress((void**)&r2_ptr, g_r2);

    cudaFuncSetAttribute(deform_mma_kernel,
                         cudaFuncAttributeMaxDynamicSharedMemorySize, DSM_BYTES);

    // w2 -> bf16 hi/lo, k = tap*256+c
    prep_w2_kernel<<<(CB * KD + 255) / 256, 256>>>(w2);

    // conv1: 1024 -> 256, relu (HMMA split-bf16)
    gemm_tc_kernel<<<dim3(HW / 64, CB / 128, Nn), 256>>>(
        w1, x, b1, nullptr, r_ptr, CB, CIN);

    // offset conv 3x3: 256 -> 18
    offset_conv_kernel<<<dim3(HW / 64, Nn), 256>>>(w_off, b_off);

    // deformable conv 3x3: 256 -> 256, relu (HMMA split-bf16)
    deform_mma_kernel<<<dim3(HW / 64, 2, Nn), 256, DSM_BYTES>>>(b2);

    // conv3: 256 -> 1024 + x residual, relu (HMMA split-bf16)
    gemm_tc_kernel<<<dim3(HW / 64, CIN / 128, Nn), 256>>>(
        w3, r2_ptr, b3, x, out, CIN, CB);
}

// round 6
// speedup vs baseline: 1.7518x; 1.0700x over previous
#include <cuda_runtime.h>
#include <cuda_bf16.h>
#include <math.h>
#include <stdint.h>

#define Nn   4
#define CIN  1024
#define CB   256
#define Hh   56
#define Ww   56
#define HW   3136
#define KT   9
#define KD   (CB * KT)   // 2304

// Scratch (device globals: allocation-free rule)
__device__ float g_r  [Nn * CB * HW];     // conv1 output (relu)
__device__ float g_off[Nn * 2 * KT * HW]; // offset conv output
__device__ float g_r2 [Nn * CB * HW];     // deform conv output (relu)
__device__ __nv_bfloat16 g_w2h[CB * KD];  // w2 split hi, [o][tap*256+c]
__device__ __nv_bfloat16 g_w2l[CB * KD];  // w2 split lo

// ---------------------------------------------------------------------------
// helpers
// ---------------------------------------------------------------------------
__device__ __forceinline__ void split2(float x, float y, uint32_t& hi, uint32_t& lo) {
    __nv_bfloat16 xh = __float2bfloat16(x);
    __nv_bfloat16 yh = __float2bfloat16(y);
    __nv_bfloat16 xl = __float2bfloat16(x - __bfloat162float(xh));
    __nv_bfloat16 yl = __float2bfloat16(y - __bfloat162float(yh));
    hi = ((uint32_t)__bfloat16_as_ushort(yh) << 16) | __bfloat16_as_ushort(xh);
    lo = ((uint32_t)__bfloat16_as_ushort(yl) << 16) | __bfloat16_as_ushort(xl);
}
__device__ __forceinline__ void split8(const float4& a, const float4& b,
                                       uint4& hi, uint4& lo) {
    split2(a.x, a.y, hi.x, lo.x);
    split2(a.z, a.w, hi.y, lo.y);
    split2(b.x, b.y, hi.z, lo.z);
    split2(b.z, b.w, hi.w, lo.w);
}

__device__ __forceinline__ void mma16816(float* c, const uint32_t* a, const uint32_t* b) {
    asm volatile(
        "mma.sync.aligned.m16n8k16.row.col.f32.bf16.bf16.f32 "
        "{%0,%1,%2,%3}, {%4,%5,%6,%7}, {%8,%9}, {%0,%1,%2,%3};"
        : "+f"(c[0]), "+f"(c[1]), "+f"(c[2]), "+f"(c[3])
        : "r"(a[0]), "r"(a[1]), "r"(a[2]), "r"(a[3]), "r"(b[0]), "r"(b[1]));
}

__device__ __forceinline__ void ldsm_x4(uint32_t* r, uint32_t addr) {
    asm volatile("ldmatrix.sync.aligned.m8n8.x4.shared.b16 {%0,%1,%2,%3}, [%4];"
                 : "=r"(r[0]), "=r"(r[1]), "=r"(r[2]), "=r"(r[3]) : "r"(addr));
}
__device__ __forceinline__ void ldsm_x2(uint32_t* r, uint32_t addr) {
    asm volatile("ldmatrix.sync.aligned.m8n8.x2.shared.b16 {%0,%1}, [%2];"
                 : "=r"(r[0]), "=r"(r[1]) : "r"(addr));
}
template <int P>
__device__ __forceinline__ uint32_t a_addr(__nv_bfloat16 (*S)[P], int mb, int ks, int ln) {
    int row = mb + (ln & 7) + ((ln >> 3) & 1) * 8;
    int col = ks + (ln >> 4) * 8;
    return (uint32_t)__cvta_generic_to_shared(&S[row][col]);
}
template <int P>
__device__ __forceinline__ uint32_t b_addr(__nv_bfloat16 (*S)[P], int nb, int ks, int ln) {
    int l = ln & 15;
    int row = nb + (l & 7);
    int col = ks + ((l >> 3) & 1) * 8;
    return (uint32_t)__cvta_generic_to_shared(&S[row][col]);
}
__device__ __forceinline__ void cp16(uint32_t saddr, const void* g) {
    asm volatile("cp.async.ca.shared.global [%0], [%1], 16;"
                 :: "r"(saddr), "l"(g) : "memory");
}
#define CP_COMMIT() asm volatile("cp.async.commit_group;" ::: "memory")
#define CP_WAIT0()  asm volatile("cp.async.wait_group 0;" ::: "memory")

// ---------------------------------------------------------------------------
// w2 (o,c,kh,kw) fp32 -> bf16 hi/lo at [o][tap*256+c]
// ---------------------------------------------------------------------------
__global__ void prep_w2_kernel(const float* __restrict__ w2) {
    int i = blockIdx.x * 256 + threadIdx.x;
    if (i < CB * KD) {
        int o = i / KD;
        int k = i % KD;
        int tap = k >> 8;
        int c   = k & 255;
        float v = w2[(o * CB + c) * KT + tap];
        __nv_bfloat16 h = __float2bfloat16(v);
        g_w2h[i] = h;
        g_w2l[i] = __float2bfloat16(v - __bfloat162float(h));
    }
}

// ===========================================================================
// Tensor-core (HMMA) GEMM for the 1x1 convs. ldmatrix fragment loads.
// ===========================================================================
#define BKP 40

__global__ __launch_bounds__(256) void gemm_tc_kernel(
        const float* __restrict__ A, const float* __restrict__ Bx,
        const float* __restrict__ bias, const float* __restrict__ resid,
        float* __restrict__ C, int M, int Kd) {
    __shared__ __nv_bfloat16 As_hi[128][BKP];
    __shared__ __nv_bfloat16 As_lo[128][BKP];
    __shared__ __nv_bfloat16 Bs_hi[64][BKP];
    __shared__ __nv_bfloat16 Bs_lo[64][BKP];

    const int n  = blockIdx.z;
    const int m0 = blockIdx.y * 128;
    const int p0 = blockIdx.x * 64;
    const int tid = threadIdx.x;
    const int wid = tid >> 5;
    const int lid = tid & 31;
    const int q = lid >> 2;
    const int r = lid & 3;
    const int warp_m = wid >> 2;
    const int warp_n = wid & 3;
    const float* Bn = Bx + (size_t)n * Kd * HW;

    const int a_row0 = tid >> 2;
    const int a_kg   = (tid & 3) * 8;
    const int b_k   = (tid & 15) * 2;
    const int b_px  = (tid >> 4) * 4;

    float acc[4][2][4] = {};
    const int KC = Kd >> 5;

    float4 ga[2][2], gb[2];
    {
        const float* g0 = A + (size_t)(m0 + a_row0) * Kd + a_kg;
        ga[0][0] = *(const float4*)g0;
        ga[0][1] = *(const float4*)(g0 + 4);
        const float* g1 = A + (size_t)(m0 + a_row0 + 64) * Kd + a_kg;
        ga[1][0] = *(const float4*)g1;
        ga[1][1] = *(const float4*)(g1 + 4);
        const float* gB = Bn + (size_t)b_k * HW + p0 + b_px;
        gb[0] = *(const float4*)gB;
        gb[1] = *(const float4*)(gB + HW);
    }

    for (int kc = 0; kc < KC; ++kc) {
        __syncthreads();
#pragma unroll
        for (int t = 0; t < 2; ++t) {
            int row = a_row0 + t * 64;
            uint4 hi, lo;
            split8(ga[t][0], ga[t][1], hi, lo);
            *(uint4*)&As_hi[row][a_kg] = hi;
            *(uint4*)&As_lo[row][a_kg] = lo;
        }
        {
            float vk[4]  = {gb[0].x, gb[0].y, gb[0].z, gb[0].w};
            float vk1[4] = {gb[1].x, gb[1].y, gb[1].z, gb[1].w};
#pragma unroll
            for (int j = 0; j < 4; ++j) {
                uint32_t hi, lo;
                split2(vk[j], vk1[j], hi, lo);
                *(uint32_t*)&Bs_hi[b_px + j][b_k] = hi;
                *(uint32_t*)&Bs_lo[b_px + j][b_k] = lo;
            }
        }
        __syncthreads();

        if (kc + 1 < KC) {
            const int k0 = (kc + 1) << 5;
            const float* g0 = A + (size_t)(m0 + a_row0) * Kd + k0 + a_kg;
            ga[0][0] = *(const float4*)g0;
            ga[0][1] = *(const float4*)(g0 + 4);
            const float* g1 = A + (size_t)(m0 + a_row0 + 64) * Kd + k0 + a_kg;
            ga[1][0] = *(const float4*)g1;
            ga[1][1] = *(const float4*)(g1 + 4);
            const float* gB = Bn + (size_t)(k0 + b_k) * HW + p0 + b_px;
            gb[0] = *(const float4*)gB;
            gb[1] = *(const float4*)(gB + HW);
        }

#pragma unroll
        for (int ks = 0; ks < 32; ks += 16) {
            uint32_t bf_hi[2][2], bf_lo[2][2];
#pragma unroll
            for (int nf = 0; nf < 2; ++nf) {
                int nb = warp_n * 16 + nf * 8;
                ldsm_x2(bf_hi[nf], b_addr(Bs_hi, nb, ks, lid));
                ldsm_x2(bf_lo[nf], b_addr(Bs_lo, nb, ks, lid));
            }
#pragma unroll
            for (int mf = 0; mf < 4; ++mf) {
                int mb = warp_m * 64 + mf * 16;
                uint32_t ah[4], al[4];
                ldsm_x4(ah, a_addr(As_hi, mb, ks, lid));
                ldsm_x4(al, a_addr(As_lo, mb, ks, lid));
#pragma unroll
                for (int nf = 0; nf < 2; ++nf) {
                    mma16816(acc[mf][nf], ah, bf_hi[nf]);
                    mma16816(acc[mf][nf], ah, bf_lo[nf]);
                    mma16816(acc[mf][nf], al, bf_hi[nf]);
                }
            }
        }
    }

#pragma unroll
    for (int mf = 0; mf < 4; ++mf) {
#pragma unroll
        for (int nf = 0; nf < 2; ++nf) {
            int m  = m0 + warp_m * 64 + mf * 16 + q;
            int px = p0 + warp_n * 16 + nf * 8 + 2 * r;
#pragma unroll
            for (int half = 0; half < 2; ++half) {
                int mm = m + half * 8;
                float c0 = acc[mf][nf][half * 2 + 0];
                float c1 = acc[mf][nf][half * 2 + 1];
                float bb = bias[mm];
                size_t base = ((size_t)n * M + mm) * HW + px;
                if (resid) {
                    float2 rv = *(const float2*)(resid + base);
                    c0 += rv.x;
                    c1 += rv.y;
                }
                float2 o;
                o.x = fmaxf(c0 + bb, 0.f);
                o.y = fmaxf(c1 + bb, 0.f);
                *(float2*)(C + base) = o;
            }
        }
    }
}

// ---------------------------------------------------------------------------
// Offset conv: 3x3 SAME, CB=256 -> 18 channels (unchanged)
// ---------------------------------------------------------------------------
__global__ void offset_conv_kernel(const float* __restrict__ w_off,
                                   const float* __restrict__ b_off) {
    __shared__ float red[8][64][18];
    const int n  = blockIdx.y;
    const int p0 = blockIdx.x * 64;
    const int tid = threadIdx.x;
    const int g  = tid >> 5;
    const int lx = tid & 31;

    float acc[2][18];
#pragma unroll
    for (int qq = 0; qq < 2; ++qq)
#pragma unroll
        for (int oc = 0; oc < 18; ++oc) acc[qq][oc] = 0.f;

    for (int ci = g; ci < CB; ci += 8) {
        const float* rb = g_r + ((size_t)n * CB + ci) * HW;
        float v[2][9];
#pragma unroll
        for (int qq = 0; qq < 2; ++qq) {
            int p = p0 + lx + qq * 32;
            int h = p / Ww, w = p % Ww;
#pragma unroll
            for (int t = 0; t < 9; ++t) {
                int y = h + t / 3 - 1;
                int x = w + t % 3 - 1;
                v[qq][t] = (y >= 0 && y < Hh && x >= 0 && x < Ww) ? rb[y * Ww + x] : 0.f;
            }
        }
        const float* wb = w_off + ci * 9;
#pragma unroll
        for (int oc = 0; oc < 18; ++oc) {
#pragma unroll
            for (int t = 0; t < 9; ++t) {
                float wv = wb[oc * (CB * 9) + t];
                acc[0][oc] += wv * v[0][t];
                acc[1][oc] += wv * v[1][t];
            }
        }
    }

#pragma unroll
    for (int qq = 0; qq < 2; ++qq)
#pragma unroll
        for (int oc = 0; oc < 18; ++oc)
            red[g][lx + qq * 32][oc] = acc[qq][oc];
    __syncthreads();

    for (int i = tid; i < 64 * 18; i += 256) {
        int ps = i / 18, oc = i % 18;
        float s = b_off[oc];
#pragma unroll
        for (int g2 = 0; g2 < 8; ++g2) s += red[g2][ps][oc];
        g_off[((size_t)n * 18 + oc) * HW + p0 + ps] = s;
    }
}

// ===========================================================================
// Deformable 3x3 conv on tensor cores, software-pipelined:
//  - gather for chunk i+1 prefetched into regs during MMA of chunk i
//  - weights staged via cp.async (no register cost)
//  - ldmatrix fragment loads
// k = tap*256 + c; chunks of 64 k (one tap x 64 ch); 36 chunks.
// ===========================================================================
#define DPITCH 72
#define DSM_AS_H 0
#define DSM_AS_L 18432
#define DSM_BS_H 36864
#define DSM_BS_L 46080
#define DSM_BYTES 55296

__global__ __launch_bounds__(256, 2) void deform_mma_kernel(const float* __restrict__ b2) {
    extern __shared__ char dsm[];
    __nv_bfloat16 (*As_h)[DPITCH] = (__nv_bfloat16(*)[DPITCH])(dsm + DSM_AS_H);
    __nv_bfloat16 (*As_l)[DPITCH] = (__nv_bfloat16(*)[DPITCH])(dsm + DSM_AS_L);
    __nv_bfloat16 (*Bs_h)[DPITCH] = (__nv_bfloat16(*)[DPITCH])(dsm + DSM_BS_H);
    __nv_bfloat16 (*Bs_l)[DPITCH] = (__nv_bfloat16(*)[DPITCH])(dsm + DSM_BS_L);

    const int pb = blockIdx.x * 64;
    const int m0 = blockIdx.y * 128;
    const int n  = blockIdx.z;
    const int tid = threadIdx.x;
    const int wid = tid >> 5;
    const int lid = tid & 31;
    const int q = lid >> 2;
    const int r = lid & 3;
    const int wm = wid & 3;
    const int wn = wid >> 2;

    const int gpx = tid & 63;
    const int gg  = tid >> 6;
    const int gcl = gg * 16;

    const float* fbase = g_r + (size_t)n * CB * HW;
    const float* offb  = g_off + (size_t)n * 18 * HW + pb + gpx;
    const int gh = (pb + gpx) / Ww;
    const int gw = (pb + gpx) % Ww;

    float acc[2][4][4] = {};

    // bilinear state (registers), recomputed per tap
    int   idx0, idx1, idx2, idx3;
    float wt0, wt1, wt2, wt3;
#define BILIN(tap_) do {                                                       \
    float dy = offb[(size_t)((tap_) * 2 + 0) * HW];                            \
    float dx = offb[(size_t)((tap_) * 2 + 1) * HW];                            \
    float ys = (float)(gh + (tap_) / 3 - 1) + dy;                              \
    float xs = (float)(gw + (tap_) % 3 - 1) + dx;                              \
    float y0f = floorf(ys), x0f = floorf(xs);                                  \
    float wy1 = ys - y0f, wy0 = 1.f - wy1;                                     \
    float wx1 = xs - x0f, wx0 = 1.f - wx1;                                     \
    int y0 = (int)y0f, x0 = (int)x0f;                                          \
    int y1 = y0 + 1, x1 = x0 + 1;                                              \
    bool vy0 = (y0 >= 0) && (y0 < Hh);                                         \
    bool vy1 = (y1 >= 0) && (y1 < Hh);                                         \
    bool vx0 = (x0 >= 0) && (x0 < Ww);                                         \
    bool vx1 = (x1 >= 0) && (x1 < Ww);                                         \
    int yc0 = min(max(y0, 0), Hh - 1), yc1 = min(max(y1, 0), Hh - 1);          \
    int xc0 = min(max(x0, 0), Ww - 1), xc1 = min(max(x1, 0), Ww - 1);          \
    idx0 = yc0 * Ww + xc0;  wt0 = (vy0 && vx0) ? wy0 * wx0 : 0.f;              \
    idx1 = yc0 * Ww + xc1;  wt1 = (vy0 && vx1) ? wy0 * wx1 : 0.f;              \
    idx2 = yc1 * Ww + xc0;  wt2 = (vy1 && vx0) ? wy1 * wx0 : 0.f;              \
    idx3 = yc1 * Ww + xc1;  wt3 = (vy1 && vx1) ? wy1 * wx1 : 0.f;              \
} while (0)

    float v[16];
#define GATHER(c0_) do {                                                       \
    _Pragma("unroll")                                                          \
    for (int j = 0; j < 16; ++j) {                                             \
        const float* f = fbase + (size_t)((c0_) + gcl + j) * HW;               \
        v[j] = wt0 * __ldg(f + idx0) + wt1 * __ldg(f + idx1)                   \
             + wt2 * __ldg(f + idx2) + wt3 * __ldg(f + idx3);                  \
    }                                                                          \
} while (0)

    // prologue: chunk 0
    BILIN(0);
    GATHER(0);
    int tap_cur = 0;

    for (int ch = 0; ch < 36; ++ch) {
        const int tap = ch >> 2;
        const int k0  = tap * 256 + (ch & 3) * 64;
        __syncthreads();  // previous MMA done with smem

        // store gathered values -> Bs (split bf16 hi/lo)
        {
            uint4 h0, h1, l0, l1;
            split2(v[0],  v[1],  h0.x, l0.x);
            split2(v[2],  v[3],  h0.y, l0.y);
            split2(v[4],  v[5],  h0.z, l0.z);
            split2(v[6],  v[7],  h0.w, l0.w);
            split2(v[8],  v[9],  h1.x, l1.x);
            split2(v[10], v[11], h1.y, l1.y);
            split2(v[12], v[13], h1.z, l1.z);
            split2(v[14], v[15], h1.w, l1.w);
            *(uint4*)&Bs_h[gpx][gcl]     = h0;
            *(uint4*)&Bs_h[gpx][gcl + 8] = h1;
            *(uint4*)&Bs_l[gpx][gcl]     = l0;
            *(uint4*)&Bs_l[gpx][gcl + 8] = l1;
        }
        // stage weights via cp.async
#pragma unroll
        for (int pass = 0; pass < 4; ++pass) {
            int id   = tid + pass * 256;
            int row  = id >> 3;
            int col  = (id & 7) * 8;
            size_t goff = (size_t)(m0 + row) * KD + k0 + col;
            cp16((uint32_t)__cvta_generic_to_shared(&As_h[row][col]), g_w2h + goff);
            cp16((uint32_t)__cvta_generic_to_shared(&As_l[row][col]), g_w2l + goff);
        }
        CP_COMMIT();

        // prefetch next chunk's gather while cp.async + MMA proceed
        if (ch + 1 < 36) {
            int ntap = (ch + 1) >> 2;
            if (ntap != tap_cur) {
                BILIN(ntap);
                tap_cur = ntap;
            }
            GATHER(((ch + 1) & 3) * 64);
        }

        CP_WAIT0();
        __syncthreads();

        // MMA: 4 k16 steps over the 64-k chunk (ldmatrix fragments)
#pragma unroll
        for (int ks = 0; ks < 64; ks += 16) {
            uint32_t bh[4][2], bl[4][2];
#pragma unroll
            for (int nf = 0; nf < 4; ++nf) {
                int nb = wn * 32 + nf * 8;
                ldsm_x2(bh[nf], b_addr(Bs_h, nb, ks, lid));
                ldsm_x2(bl[nf], b_addr(Bs_l, nb, ks, lid));
            }
#pragma unroll
            for (int mf = 0; mf < 2; ++mf) {
                int mb = wm * 32 + mf * 16;
                uint32_t ah[4], al[4];
                ldsm_x4(ah, a_addr(As_h, mb, ks, lid));
                ldsm_x4(al, a_addr(As_l, mb, ks, lid));
#pragma unroll
                for (int nf = 0; nf < 4; ++nf) {
                    mma16816(acc[mf][nf], ah, bh[nf]);
                    mma16816(acc[mf][nf], ah, bl[nf]);
                    mma16816(acc[mf][nf], al, bh[nf]);
                }
            }
        }
    }

    // epilogue: bias + relu -> g_r2
#pragma unroll
    for (int mf = 0; mf < 2; ++mf) {
#pragma unroll
        for (int half = 0; half < 2; ++half) {
            int o = m0 + wm * 32 + mf * 16 + q + half * 8;
            float bb = b2[o];
            float* orow = g_r2 + ((size_t)n * CB + o) * HW + pb;
#pragma unroll
            for (int nf = 0; nf < 4; ++nf) {
                int px = wn * 32 + nf * 8 + 2 * r;
                float2 ov;
                ov.x = fmaxf(acc[mf][nf][half * 2 + 0] + bb, 0.f);
                ov.y = fmaxf(acc[mf][nf][half * 2 + 1] + bb, 0.f);
                *(float2*)(orow + px) = ov;
            }
        }
    }
}

// ---------------------------------------------------------------------------
extern "C" void kernel_launch(void* const* d_in, const int* in_sizes, int n_in,
                              void* d_out, int out_size) {
    const float* x     = (const float*)d_in[0];
    const float* w1    = (const float*)d_in[1];
    const float* b1    = (const float*)d_in[2];
    const float* w_off = (const float*)d_in[3];
    const float* b_off = (const float*)d_in[4];
    const float* w2    = (const float*)d_in[5];
    const float* b2    = (const float*)d_in[6];
    const float* w3    = (const float*)d_in[7];
    const float* b3    = (const float*)d_in[8];
    float* out = (float*)d_out;

    float *r_ptr, *r2_ptr;
    cudaGetSymbolAddress((void**)&r_ptr, g_r);
    cudaGetSymbolAddress((void**)&r2_ptr, g_r2);

    cudaFuncSetAttribute(deform_mma_kernel,
                         cudaFuncAttributeMaxDynamicSharedMemorySize, DSM_BYTES);

    // w2 -> bf16 hi/lo, k = tap*256+c
    prep_w2_kernel<<<(CB * KD + 255) / 256, 256>>>(w2);

    // conv1: 1024 -> 256, relu (HMMA split-bf16)
    gemm_tc_kernel<<<dim3(HW / 64, CB / 128, Nn), 256>>>(
        w1, x, b1, nullptr, r_ptr, CB, CIN);

    // offset conv 3x3: 256 -> 18
    offset_conv_kernel<<<dim3(HW / 64, Nn), 256>>>(w_off, b_off);

    // deformable conv 3x3: 256 -> 256, relu (HMMA split-bf16, pipelined)
    deform_mma_kernel<<<dim3(HW / 64, 2, Nn), 256, DSM_BYTES>>>(b2);

    // conv3: 256 -> 1024 + x residual, relu (HMMA split-bf16)
    gemm_tc_kernel<<<dim3(HW / 64, CIN / 128, Nn), 256>>>(
        w3, r2_ptr, b3, x, out, CIN, CB);
}